// round 3
// baseline (speedup 1.0000x reference)
#include <cuda_runtime.h>
#include <math.h>

#define S_ 64
#define C_ 256
#define NN_ 4096
#define B_ 16
#define M_ 128
#define P_ 2080
#define TINV 10.0f
#define NEGIOU 0.5f
#define PTILES 17
#define TP 128
#define CK 16
#define QBLOCKS (B_*PTILES)

// scratch (device globals; no allocation allowed)
__device__ int   g_midx[P_];
__device__ int   g_b2s[B_];
__device__ int   g_m2s[M_];
__device__ int   g_s2b[S_];
__device__ float g_sfn[S_*C_];
__device__ float g_pl[M_];
__device__ float g_lossv[M_];
__device__ float g_qpart[QBLOCKS*S_];
__device__ float g_qneg[S_];

// ---------------------------------------------------------------------------
// Kernel 1: analytic triu(64x64) mask indices + scatter maps.
// mask2d is static config (upper-triangular incl. diagonal, P=2080) — we do
// NOT read the mask buffer (its storage dtype is ambiguous in the harness).
// ---------------------------------------------------------------------------
__global__ void setup_kernel(const int* __restrict__ nsent,
                             const int* __restrict__ ntarg) {
    int r = threadIdx.x;          // 64 threads, one row each
    if (r < 64) {
        // offset of row r in the row-major nonzero order: sum_{i<r}(64-i)
        int off = r * 64 - (r * (r - 1)) / 2;
        for (int c = r; c < 64; c++)
            g_midx[off + (c - r)] = r * 64 + c;
    }
    if (r == 0) {
        int acc = 0;
        for (int b = 0; b < B_; b++) {
            g_b2s[b] = acc;
            for (int j = 0; j < nsent[b]; j++)
                if (acc + j < S_) g_s2b[acc + j] = b;
            acc += nsent[b];
        }
        int mi = 0;
        for (int s = 0; s < S_; s++)
            for (int j = 0; j < ntarg[s]; j++)
                if (mi < M_) g_m2s[mi++] = s;
    }
}

// ---------------------------------------------------------------------------
// Kernel 2: normalize sentence features  (64 blocks x 256 threads)
// ---------------------------------------------------------------------------
__global__ void sfnorm_kernel(const float* __restrict__ sf) {
    int s = blockIdx.x;
    int t = threadIdx.x; // == c
    float v = sf[s * C_ + t];
    float x = v * v;
#pragma unroll
    for (int o = 16; o; o >>= 1) x += __shfl_down_sync(0xffffffffu, x, o);
    __shared__ float red[8];
    if ((t & 31) == 0) red[t >> 5] = x;
    __syncthreads();
    if (t == 0) {
        float acc = 0.f;
#pragma unroll
        for (int i = 0; i < 8; i++) acc += red[i];
        red[0] = acc;
    }
    __syncthreads();
    float n = fmaxf(sqrtf(red[0]), 1e-12f);
    g_sfn[s * C_ + t] = v / n;
}

// ---------------------------------------------------------------------------
// Kernel 3: per-moment top-1 proposal + inter-video loss (128 blocks x 256 thr)
// ---------------------------------------------------------------------------
__global__ void video_kernel(const float* __restrict__ video,
                             const float* __restrict__ iou2ds) {
    int m = blockIdx.x;
    int t = threadIdx.x;
    int sm = g_m2s[m];

    // ---- argmax over P of iou2ds[m, midx[p]] (tie -> lowest p) ----
    float best = -1e30f;
    int bi = 0;
    for (int p = t; p < P_; p += 256) {
        float v = iou2ds[m * NN_ + g_midx[p]];
        if (v > best) { best = v; bi = p; }
    }
    __shared__ float sv[256];
    __shared__ int   sidx[256];
    sv[t] = best; sidx[t] = bi;
    __syncthreads();
    for (int o = 128; o; o >>= 1) {
        if (t < o) {
            float vo = sv[t + o]; int io = sidx[t + o];
            if (vo > sv[t] || (vo == sv[t] && io < sidx[t])) { sv[t] = vo; sidx[t] = io; }
        }
        __syncthreads();
    }
    int pflat = g_midx[sidx[0]];
    __syncthreads();

    // ---- load v[c], normalize ----
    float vc = video[((size_t)sm * C_ + t) * NN_ + pflat];
    float x = vc * vc;
#pragma unroll
    for (int o = 16; o; o >>= 1) x += __shfl_down_sync(0xffffffffu, x, o);
    __shared__ float red[8];
    if ((t & 31) == 0) red[t >> 5] = x;
    __syncthreads();
    if (t == 0) {
        float acc = 0.f;
#pragma unroll
        for (int i = 0; i < 8; i++) acc += red[i];
        red[0] = acc;
    }
    __syncthreads();
    float nrm = fmaxf(sqrtf(red[0]), 1e-12f);
    sv[t] = vc / nrm;
    __syncthreads();

    // ---- dots against all 64 normalized sentence vectors ----
    __shared__ float alls[S_];
    int w = t >> 5, l = t & 31;
#pragma unroll
    for (int k = 0; k < 8; k++) {
        int s = w * 8 + k;
        float acc = 0.f;
#pragma unroll
        for (int c = l; c < C_; c += 32) acc += sv[c] * g_sfn[s * C_ + c];
#pragma unroll
        for (int o = 16; o; o >>= 1) acc += __shfl_down_sync(0xffffffffu, acc, o);
        if (l == 0) alls[s] = acc;
    }
    __syncthreads();
    if (t == 0) {
        float pl = alls[sm] * TINV;
        float neg = 0.f;
        for (int s = 0; s < S_; s++)
            if (s != sm) neg += expf(alls[s] * TINV);
        g_pl[m] = pl;
        g_lossv[m] = logf(expf(pl) + neg) - pl;
    }
}

// ---------------------------------------------------------------------------
// Kernel 4: inter-query fused GEMM + masked exp-sum
// grid (PTILES, B), 128 threads; 64s x 128p tile, 8x8 micro-tile/thread
// ---------------------------------------------------------------------------
__global__ __launch_bounds__(128) void query_kernel(const float* __restrict__ video,
                                                    const float* __restrict__ iou2d) {
    int pt = blockIdx.x;
    int b  = blockIdx.y;
    int sb = g_b2s[b];
    int tid = threadIdx.x;
    int pi = tid & 15;   // p-group 0..15 (thread's p's: pi + 16*j)
    int si = tid >> 4;   // s-group 0..7  (thread's s's: si*8 + a)

    __shared__ float sfc[CK * S_];      // [cc][s]   4KB
    __shared__ float vt[CK][TP];        // [cc][p]   8KB
    __shared__ float part[S_][16];      //           4KB

    int ptbase = pt * TP;
    int pcol = ptbase + tid;            // column this thread loads
    int fidx = (pcol < P_) ? g_midx[pcol] : -1;
    const float* vbase = video + (size_t)sb * C_ * NN_;

    float acc[8][8];
    float accn[8];
#pragma unroll
    for (int a = 0; a < 8; a++)
#pragma unroll
        for (int j = 0; j < 8; j++) acc[a][j] = 0.f;
#pragma unroll
    for (int j = 0; j < 8; j++) accn[j] = 0.f;

    for (int cb = 0; cb < C_; cb += CK) {
        // load v tile (coalesced gather over p)
#pragma unroll
        for (int i = 0; i < CK; i++)
            vt[i][tid] = (fidx >= 0) ? vbase[(size_t)(cb + i) * NN_ + fidx] : 0.f;
        // load sf chunk transposed: sfc[i*64+s] = sfn[s][cb+i]
#pragma unroll
        for (int k = 0; k < (CK * S_) / 128; k++) {
            int idx = tid + k * 128;
            int i = idx >> 6, s = idx & 63;
            sfc[idx] = g_sfn[s * C_ + cb + i];
        }
        __syncthreads();
#pragma unroll
        for (int i = 0; i < CK; i++) {
            float vv[8], ss[8];
#pragma unroll
            for (int j = 0; j < 8; j++) vv[j] = vt[i][pi + 16 * j];
            float4 s0 = *(const float4*)&sfc[i * 64 + si * 8];
            float4 s1 = *(const float4*)&sfc[i * 64 + si * 8 + 4];
            ss[0] = s0.x; ss[1] = s0.y; ss[2] = s0.z; ss[3] = s0.w;
            ss[4] = s1.x; ss[5] = s1.y; ss[6] = s1.z; ss[7] = s1.w;
#pragma unroll
            for (int j = 0; j < 8; j++) accn[j] = fmaf(vv[j], vv[j], accn[j]);
#pragma unroll
            for (int a = 0; a < 8; a++)
#pragma unroll
                for (int j = 0; j < 8; j++)
                    acc[a][j] = fmaf(ss[a], vv[j], acc[a][j]);
        }
        __syncthreads();
    }

    // epilogue: score = dot / ||v||; masked exp-sum per s
    float inv[8];
#pragma unroll
    for (int j = 0; j < 8; j++)
        inv[j] = 1.f / fmaxf(sqrtf(accn[j]), 1e-12f);

#pragma unroll
    for (int a = 0; a < 8; a++) {
        int s = si * 8 + a;
        bool samevid = (g_s2b[s] == b);
        float sum = 0.f;
#pragma unroll
        for (int j = 0; j < 8; j++) {
            int p = ptbase + pi + 16 * j;
            if (p < P_) {
                bool excl = false;
                if (samevid) {
                    float io = iou2d[s * NN_ + g_midx[p]];
                    excl = (io > NEGIOU);
                }
                if (!excl) sum += expf(acc[a][j] * inv[j] * TINV);
            }
        }
        part[s][pi] = sum;
    }
    __syncthreads();
    if (tid < S_) {
        float tot = 0.f;
#pragma unroll
        for (int k = 0; k < 16; k++) tot += part[tid][k];
        g_qpart[(b * PTILES + pt) * S_ + tid] = tot;
    }
}

// ---------------------------------------------------------------------------
// Kernel 5: deterministic reduce of query partials per sentence
// ---------------------------------------------------------------------------
__global__ void qreduce_kernel() {
    int s = threadIdx.x;
    float t = 0.f;
    for (int i = 0; i < QBLOCKS; i++) t += g_qpart[i * S_ + s];
    g_qneg[s] = t;
}

// ---------------------------------------------------------------------------
// Kernel 6: per-moment losses -> mean  (1 block x 128 threads)
// ---------------------------------------------------------------------------
__global__ void final_kernel(float* __restrict__ out) {
    int t = threadIdx.x; // == m
    float pl = g_pl[t];
    float lq = logf(expf(pl) + g_qneg[g_m2s[t]]) - pl;
    float v = g_lossv[t] + lq;
#pragma unroll
    for (int o = 16; o; o >>= 1) v += __shfl_down_sync(0xffffffffu, v, o);
    __shared__ float red[4];
    if ((t & 31) == 0) red[t >> 5] = v;
    __syncthreads();
    if (t == 0)
        out[0] = (red[0] + red[1] + red[2] + red[3]) / (float)M_;
}

// ---------------------------------------------------------------------------
extern "C" void kernel_launch(void* const* d_in, const int* in_sizes, int n_in,
                              void* d_out, int out_size) {
    const float* video = (const float*)d_in[0];         // (S,C,N,N)
    const float* sents = (const float*)d_in[1];         // (S,C)
    const float* iou2d = (const float*)d_in[2];         // (S,N,N)
    const float* iou2ds = (const float*)d_in[3];        // (M,N,N)
    const int* nsent = (const int*)d_in[4];             // (B,)
    const int* ntarg = (const int*)d_in[5];             // (S,)
    float* out = (float*)d_out;

    setup_kernel<<<1, 64>>>(nsent, ntarg);
    sfnorm_kernel<<<S_, 256>>>(sents);
    video_kernel<<<M_, 256>>>(video, iou2ds);
    query_kernel<<<dim3(PTILES, B_), 128>>>(video, iou2d);
    qreduce_kernel<<<1, S_>>>();
    final_kernel<<<1, M_>>>(out);
}